// round 3
// baseline (speedup 1.0000x reference)
#include <cuda_runtime.h>
#include <math.h>

// B=32, N=64, ATTR=4, STATE=8, REL=4, GDIM=32, NF=128, pstep=2
#define NNODES 2048

// ---------------- scratch (static device memory) ----------------
__device__ float g_E[2048 * 64 * 128];     // E = W_rel @ rel_encode, [bi][j][f] (64 MB)
__device__ float g_obj[2048 * 128];
__device__ float g_u[2048 * 128];
__device__ float g_vt[32 * 128 * 64];      // [b][k][n]
__device__ float g_R[2048 * 128];
__device__ float g_S[2048 * 128];
__device__ float g_agg[2048 * 128];
// weights
__device__ float g_w1toe[128 * 128];       // oe_w1 transposed [k][f]
__device__ double g_w1d[128 * 128];        // re_w1 transposed + f-duplicated: [k][(w_f,w_f)]
__device__ double g_wrd[128 * 128];        // rp_w rel-block transposed + duplicated
__device__ float g_wrs[128 * 256];         // [k][ recv f (128) | send f (128) ]
__device__ float g_ppwt[256 * 128];        // pp_w transposed [k][f]
__device__ float g_prw0t[128 * 128];
__device__ float g_prw1t[128 * 32];

// packed f32x2 FMA: d = a*b + c per 32-bit half
__device__ __forceinline__ double ffma2(double a, double b, double c) {
    double d;
    asm("fma.rn.f32x2 %0, %1, %2, %3;" : "=d"(d) : "d"(a), "d"(b), "d"(c));
    return d;
}
union F2D { double d; float2 f; };

// ---------------- weight prep ----------------
__global__ void prep_kernel(const float* __restrict__ oe_w1,
                            const float* __restrict__ re_w1,
                            const float* __restrict__ rp_w,
                            const float* __restrict__ pp_w,
                            const float* __restrict__ pr_w0,
                            const float* __restrict__ pr_w1) {
    int m = blockIdx.x;
    int t = threadIdx.x;
    if (m == 0) {
        for (int i = t; i < 128 * 128; i += 256) {
            int k = i >> 7, f = i & 127;
            g_w1toe[i] = oe_w1[f * 128 + k];
        }
    } else if (m == 1) {
        float* p = (float*)g_w1d;
        for (int i = t; i < 128 * 128; i += 256) {
            int k = i >> 7, f = i & 127;
            float w = re_w1[f * 128 + k];
            p[k * 256 + 2 * f] = w;
            p[k * 256 + 2 * f + 1] = w;
        }
    } else if (m == 2) {
        float* p = (float*)g_wrd;
        for (int i = t; i < 128 * 128; i += 256) {
            int k = i >> 7, f = i & 127;
            float w = rp_w[f * 384 + k];
            p[k * 256 + 2 * f] = w;
            p[k * 256 + 2 * f + 1] = w;
        }
    } else if (m == 3) {
        for (int i = t; i < 128 * 128; i += 256) {
            int k = i >> 7, f = i & 127;
            g_wrs[k * 256 + f]       = rp_w[f * 384 + 128 + k];
            g_wrs[k * 256 + 128 + f] = rp_w[f * 384 + 256 + k];
        }
    } else if (m == 4) {
        for (int i = t; i < 256 * 128; i += 256) {
            int k = i >> 7, f = i & 127;
            g_ppwt[i] = pp_w[f * 256 + k];
        }
    } else if (m == 5) {
        for (int i = t; i < 128 * 128; i += 256) {
            int k = i >> 7, f = i & 127;
            g_prw0t[i] = pr_w0[f * 128 + k];
        }
    } else {
        for (int i = t; i < 128 * 32; i += 256) {
            int k = i >> 5, o = i & 31;
            g_prw1t[i] = pr_w1[o * 128 + k];
        }
    }
}

// ---------------- per-node parts of rel layer0 ----------------
__global__ void node_pre_kernel(const float* __restrict__ attrs,
                                const float* __restrict__ states,
                                const float* __restrict__ re_w0,
                                const float* __restrict__ re_b0) {
    int node = blockIdx.x;
    int f = threadIdx.x;
    __shared__ float sa[4];
    __shared__ float ss[8];
    if (f < 4) sa[f] = attrs[node * 4 + f];
    if (f >= 4 && f < 12) ss[f - 4] = states[node * 8 + (f - 4)];
    __syncthreads();
    const float* w = re_w0 + f * 20;  // [rel(4) | dstate(8) | recv_attr(4) | send_attr(4)]
    float u = re_b0[f];
    float v = 0.f;
#pragma unroll
    for (int c = 0; c < 8; c++) {
        float wc = w[4 + c];
        u += wc * ss[c];
        v -= wc * ss[c];
    }
#pragma unroll
    for (int c = 0; c < 4; c++) {
        u += w[12 + c] * sa[c];
        v += w[16 + c] * sa[c];
    }
    g_u[node * 128 + f] = u;
    int b = node >> 6, n = node & 63;
    g_vt[(b * 128 + f) * 64 + n] = v;
}

// ---------------- batched object encoder: 16 nodes/block ----------------
__global__ __launch_bounds__(256) void encode_batched(const float* __restrict__ attrs,
                                                      const float* __restrict__ states,
                                                      const float* __restrict__ oe_w0,
                                                      const float* __restrict__ oe_b0,
                                                      const float* __restrict__ oe_b1) {
    __shared__ float W0s[128 * 12];
    __shared__ float b0s[128];
    __shared__ float xs[16 * 12];
    __shared__ float Hs[128 * 21];  // layer1 out transposed [f][n]
    int base = blockIdx.x * 16;
    int tid = threadIdx.x;
    for (int i = tid; i < 128 * 12; i += 256) W0s[i] = oe_w0[i];
    if (tid < 128) b0s[tid] = oe_b0[tid];
    if (tid < 16 * 12) {
        int n = tid / 12, c = tid % 12;
        xs[tid] = (c < 4) ? attrs[(base + n) * 4 + c] : states[(base + n) * 8 + (c - 4)];
    }
    __syncthreads();
    {
        int f = tid & 127, ng = tid >> 7;
#pragma unroll
        for (int i = 0; i < 8; i++) {
            int n = ng * 8 + i;
            float h = b0s[f];
#pragma unroll
            for (int c = 0; c < 12; c++) h += W0s[f * 12 + c] * xs[n * 12 + c];
            Hs[f * 21 + n] = fmaxf(h, 0.f);
        }
    }
    __syncthreads();
    int tx = tid & 31, ty = tid >> 5;  // f = 4tx, n = 2ty+{0,1}
    float acc[2][4];
#pragma unroll
    for (int r = 0; r < 2; r++)
#pragma unroll
        for (int c = 0; c < 4; c++) acc[r][c] = 0.f;
#pragma unroll 4
    for (int k = 0; k < 128; k++) {
        float a0 = Hs[k * 21 + 2 * ty];
        float a1 = Hs[k * 21 + 2 * ty + 1];
        float4 w = *(const float4*)&g_w1toe[k * 128 + 4 * tx];
        acc[0][0] += a0 * w.x; acc[0][1] += a0 * w.y; acc[0][2] += a0 * w.z; acc[0][3] += a0 * w.w;
        acc[1][0] += a1 * w.x; acc[1][1] += a1 * w.y; acc[1][2] += a1 * w.z; acc[1][3] += a1 * w.w;
    }
    float4 bv = *(const float4*)&oe_b1[4 * tx];
#pragma unroll
    for (int r = 0; r < 2; r++) {
        int n = 2 * ty + r;
        float4 o = make_float4(fmaxf(acc[r][0] + bv.x, 0.f), fmaxf(acc[r][1] + bv.y, 0.f),
                               fmaxf(acc[r][2] + bv.z, 0.f), fmaxf(acc[r][3] + bv.w, 0.f));
        *(float4*)&g_obj[(base + n) * 128 + 4 * tx] = o;
    }
}

// ---------------- fused relation encoder + edge-GEMM (f32x2 packed) ----------------
__global__ __launch_bounds__(128) void rel_fused_kernel(const float* __restrict__ rel_attrs,
                                                        const float* __restrict__ re_w0,
                                                        const float* __restrict__ re_b1) {
    __shared__ float Hs[8448];       // H[k][j] s64 -> rel[f][j] s64 -> Es[f][j] s66
    __shared__ double Wcd[2][1024];  // 8 k-rows x 128 dup-doubles
    __shared__ float Us[128];
    __shared__ float Bs[128];
    int bi = blockIdx.x;
    int tid = threadIdx.x;
    int b = bi >> 6;
    Us[tid] = g_u[bi * 128 + tid];
    Bs[tid] = re_b1[tid];

    int j = tid & 63;
    int kbase = (tid >> 6) << 6;
    const float4 rv = *(const float4*)(rel_attrs + (bi * 64 + j) * 4);
    __syncthreads();
    const float* vt = g_vt + b * (128 * 64);
#pragma unroll 4
    for (int kk = 0; kk < 64; kk++) {
        int k = kbase + kk;
        const float* w = re_w0 + k * 20;
        float val = Us[k] + vt[k * 64 + j] + rv.x * w[0] + rv.y * w[1] + rv.z * w[2] + rv.w * w[3];
        Hs[k * 64 + j] = fmaxf(val, 0.f);
    }

    int tx = tid & 7;        // j-group: j = 8*tx .. 8*tx+7
    int ty = tid >> 3;       // f-group: f = 8*ty .. 8*ty+7
    double acc[4][8];        // [j-pair][f], each double = (val_j_even, val_j_odd)

    // ================= GEMM1: rel[f][j] = relu(b1 + W1^T H) =================
    {
#pragma unroll
        for (int a = 0; a < 4; a++)
#pragma unroll
            for (int q = 0; q < 8; q++) acc[a][q] = 0.0;
        double st[8];
#pragma unroll
        for (int q = 0; q < 8; q++) st[q] = g_w1d[q * 128 + tid];
#pragma unroll
        for (int q = 0; q < 8; q++) Wcd[0][q * 128 + tid] = st[q];
        __syncthreads();
        int p = 0;
#pragma unroll 1
        for (int kc = 0; kc < 128; kc += 8) {
            bool more = (kc + 8) < 128;
            if (more) {
#pragma unroll
                for (int q = 0; q < 8; q++) st[q] = g_w1d[(kc + 8 + q) * 128 + tid];
            }
            const double* cw = Wcd[p];
#pragma unroll
            for (int k = 0; k < 8; k++) {
                double2 a0 = *(const double2*)&Hs[(kc + k) * 64 + 8 * tx];
                double2 a1 = *(const double2*)&Hs[(kc + k) * 64 + 8 * tx + 4];
                double av[4] = {a0.x, a0.y, a1.x, a1.y};
                double2 wv[4];
#pragma unroll
                for (int c = 0; c < 4; c++) wv[c] = *(const double2*)&cw[k * 128 + 8 * ty + 2 * c];
#pragma unroll
                for (int jp = 0; jp < 4; jp++) {
#pragma unroll
                    for (int c = 0; c < 4; c++) {
                        acc[jp][2 * c]     = ffma2(av[jp], wv[c].x, acc[jp][2 * c]);
                        acc[jp][2 * c + 1] = ffma2(av[jp], wv[c].y, acc[jp][2 * c + 1]);
                    }
                }
            }
            if (more) {
#pragma unroll
                for (int q = 0; q < 8; q++) Wcd[p ^ 1][q * 128 + tid] = st[q];
            }
            __syncthreads();
            p ^= 1;
        }
        // epilogue: bias + relu, store rel[f][j] (pairs are j-adjacent -> direct STS.64)
#pragma unroll
        for (int ff = 0; ff < 8; ff++) {
            float b1v = Bs[8 * ty + ff];
#pragma unroll
            for (int jp = 0; jp < 4; jp++) {
                F2D u;
                u.d = acc[jp][ff];
                u.f.x = fmaxf(u.f.x + b1v, 0.f);
                u.f.y = fmaxf(u.f.y + b1v, 0.f);
                *(double*)&Hs[(8 * ty + ff) * 64 + 8 * tx + 2 * jp] = u.d;
            }
        }
    }
    __syncthreads();

    // ================= GEMM2: E[j][f'] = Wr^T rel =================
    {
#pragma unroll
        for (int a = 0; a < 4; a++)
#pragma unroll
            for (int q = 0; q < 8; q++) acc[a][q] = 0.0;
        double st[8];
#pragma unroll
        for (int q = 0; q < 8; q++) st[q] = g_wrd[q * 128 + tid];
#pragma unroll
        for (int q = 0; q < 8; q++) Wcd[0][q * 128 + tid] = st[q];
        __syncthreads();
        int p = 0;
#pragma unroll 1
        for (int kc = 0; kc < 128; kc += 8) {
            bool more = (kc + 8) < 128;
            if (more) {
#pragma unroll
                for (int q = 0; q < 8; q++) st[q] = g_wrd[(kc + 8 + q) * 128 + tid];
            }
            const double* cw = Wcd[p];
#pragma unroll
            for (int k = 0; k < 8; k++) {
                double2 a0 = *(const double2*)&Hs[(kc + k) * 64 + 8 * tx];
                double2 a1 = *(const double2*)&Hs[(kc + k) * 64 + 8 * tx + 4];
                double av[4] = {a0.x, a0.y, a1.x, a1.y};
                double2 wv[4];
#pragma unroll
                for (int c = 0; c < 4; c++) wv[c] = *(const double2*)&cw[k * 128 + 8 * ty + 2 * c];
#pragma unroll
                for (int jp = 0; jp < 4; jp++) {
#pragma unroll
                    for (int c = 0; c < 4; c++) {
                        acc[jp][2 * c]     = ffma2(av[jp], wv[c].x, acc[jp][2 * c]);
                        acc[jp][2 * c + 1] = ffma2(av[jp], wv[c].y, acc[jp][2 * c + 1]);
                    }
                }
            }
            if (more) {
#pragma unroll
                for (int q = 0; q < 8; q++) Wcd[p ^ 1][q * 128 + tid] = st[q];
            }
            __syncthreads();
            p ^= 1;
        }
        // epilogue: store E pairs into Es[f][j] (stride 66), then transpose out
#pragma unroll
        for (int ff = 0; ff < 8; ff++) {
#pragma unroll
            for (int jp = 0; jp < 4; jp++) {
                *(double*)&Hs[(8 * ty + ff) * 66 + 8 * tx + 2 * jp] = acc[jp][ff];
            }
        }
    }
    __syncthreads();
    {
        int f4 = (tid & 31) * 4;
        int j0 = tid >> 5;
        float* outp = g_E + (long)bi * 8192;
#pragma unroll 4
        for (int it = 0; it < 16; it++) {
            int jj = j0 + it * 4;
            float4 v = make_float4(Hs[f4 * 66 + jj], Hs[(f4 + 1) * 66 + jj],
                                   Hs[(f4 + 2) * 66 + jj], Hs[(f4 + 3) * 66 + jj]);
            *(float4*)&outp[jj * 128 + f4] = v;
        }
    }
}

// ---------------- batched R/S: 16 nodes/block ----------------
__global__ __launch_bounds__(256) void rs_batched(const float* __restrict__ rp_b) {
    __shared__ float Xs[128 * 21];
    int base = blockIdx.x * 16;
    int tid = threadIdx.x;
    for (int idx = tid; idx < 16 * 128; idx += 256) {
        int n = idx >> 7, k = idx & 127;
        Xs[k * 21 + n] = g_obj[(base + n) * 128 + k];
    }
    __syncthreads();
    int tx = tid & 31, ty = tid >> 5;  // f = 8tx (0..255), n = 2ty+{0,1}
    float acc[2][8];
#pragma unroll
    for (int r = 0; r < 2; r++)
#pragma unroll
        for (int c = 0; c < 8; c++) acc[r][c] = 0.f;
#pragma unroll 4
    for (int k = 0; k < 128; k++) {
        float a0 = Xs[k * 21 + 2 * ty];
        float a1 = Xs[k * 21 + 2 * ty + 1];
        float4 w0 = *(const float4*)&g_wrs[k * 256 + 8 * tx];
        float4 w1 = *(const float4*)&g_wrs[k * 256 + 8 * tx + 4];
        float w[8] = {w0.x, w0.y, w0.z, w0.w, w1.x, w1.y, w1.z, w1.w};
#pragma unroll
        for (int c = 0; c < 8; c++) {
            acc[0][c] += a0 * w[c];
            acc[1][c] += a1 * w[c];
        }
    }
    int fo = 8 * tx;
    if (fo < 128) {
        float4 b0 = *(const float4*)&rp_b[fo];
        float4 b1 = *(const float4*)&rp_b[fo + 4];
#pragma unroll
        for (int r = 0; r < 2; r++) {
            int n = 2 * ty + r;
            *(float4*)&g_R[(base + n) * 128 + fo] =
                make_float4(acc[r][0] + b0.x, acc[r][1] + b0.y, acc[r][2] + b0.z, acc[r][3] + b0.w);
            *(float4*)&g_R[(base + n) * 128 + fo + 4] =
                make_float4(acc[r][4] + b1.x, acc[r][5] + b1.y, acc[r][6] + b1.z, acc[r][7] + b1.w);
        }
    } else {
        int fs = fo - 128;
#pragma unroll
        for (int r = 0; r < 2; r++) {
            int n = 2 * ty + r;
            *(float4*)&g_S[(base + n) * 128 + fs] =
                make_float4(acc[r][0], acc[r][1], acc[r][2], acc[r][3]);
            *(float4*)&g_S[(base + n) * 128 + fs + 4] =
                make_float4(acc[r][4], acc[r][5], acc[r][6], acc[r][7]);
        }
    }
}

// ---------------- edge apply: Y = E + R_i + S_j, LN, relu, sum over j ----------------
__global__ __launch_bounds__(128) void edge_apply_kernel(const float* __restrict__ rp_lnw,
                                                         const float* __restrict__ rp_lnb) {
    __shared__ float Rs[128];
    __shared__ float Ps[512];
    int bi = blockIdx.x;
    int tid = threadIdx.x;
    int b = bi >> 6;
    int warp = tid >> 5, lane = tid & 31;
    Rs[tid] = g_R[bi * 128 + tid];
    __syncthreads();
    float4 rv = *(const float4*)&Rs[lane * 4];
    float4 lw = *(const float4*)&rp_lnw[lane * 4];
    float4 lb = *(const float4*)&rp_lnb[lane * 4];
    const float* Ep = g_E + (long)bi * 8192;
    float ag0 = 0.f, ag1 = 0.f, ag2 = 0.f, ag3 = 0.f;
#pragma unroll 4
    for (int r = 0; r < 16; r++) {
        int j = warp * 16 + r;
        float4 e = *(const float4*)&Ep[j * 128 + lane * 4];
        float4 sv = *(const float4*)&g_S[(b * 64 + j) * 128 + lane * 4];
        float4 y = make_float4(e.x + rv.x + sv.x, e.y + rv.y + sv.y,
                               e.z + rv.z + sv.z, e.w + rv.w + sv.w);
        float s = y.x + y.y + y.z + y.w;
        float ss = y.x * y.x + y.y * y.y + y.z * y.z + y.w * y.w;
#pragma unroll
        for (int off = 16; off; off >>= 1) {
            s += __shfl_xor_sync(0xffffffffu, s, off);
            ss += __shfl_xor_sync(0xffffffffu, ss, off);
        }
        float mu = s * 0.0078125f;
        float var = ss * 0.0078125f - mu * mu;
        float rstd = rsqrtf(var + 1e-5f);
        ag0 += fmaxf((y.x - mu) * rstd * lw.x + lb.x, 0.f);
        ag1 += fmaxf((y.y - mu) * rstd * lw.y + lb.y, 0.f);
        ag2 += fmaxf((y.z - mu) * rstd * lw.z + lb.z, 0.f);
        ag3 += fmaxf((y.w - mu) * rstd * lw.w + lb.w, 0.f);
    }
    *(float4*)&Ps[warp * 128 + lane * 4] = make_float4(ag0, ag1, ag2, ag3);
    __syncthreads();
    g_agg[bi * 128 + tid] = Ps[tid] + Ps[128 + tid] + Ps[256 + tid] + Ps[384 + tid];
}

// ---------------- batched object update: 16 nodes/block ----------------
__global__ __launch_bounds__(256) void obj_update_batched(const float* __restrict__ pp_b,
                                                          const float* __restrict__ pp_lnw,
                                                          const float* __restrict__ pp_lnb) {
    __shared__ float Xs[256 * 21];
    __shared__ float Cs[16 * 132];
    int base = blockIdx.x * 16;
    int tid = threadIdx.x;
    for (int idx = tid; idx < 16 * 128; idx += 256) {
        int n = idx >> 7, k = idx & 127;
        Xs[k * 21 + n] = g_obj[(base + n) * 128 + k];
        Xs[(128 + k) * 21 + n] = g_agg[(base + n) * 128 + k];
    }
    __syncthreads();
    int tx = tid & 31, ty = tid >> 5;  // f = 4tx, n = 2ty+{0,1}
    float acc[2][4];
#pragma unroll
    for (int r = 0; r < 2; r++)
#pragma unroll
        for (int c = 0; c < 4; c++) acc[r][c] = 0.f;
#pragma unroll 4
    for (int k = 0; k < 256; k++) {
        float a0 = Xs[k * 21 + 2 * ty];
        float a1 = Xs[k * 21 + 2 * ty + 1];
        float4 w = *(const float4*)&g_ppwt[k * 128 + 4 * tx];
        acc[0][0] += a0 * w.x; acc[0][1] += a0 * w.y; acc[0][2] += a0 * w.z; acc[0][3] += a0 * w.w;
        acc[1][0] += a1 * w.x; acc[1][1] += a1 * w.y; acc[1][2] += a1 * w.z; acc[1][3] += a1 * w.w;
    }
    float4 bv = *(const float4*)&pp_b[4 * tx];
#pragma unroll
    for (int r = 0; r < 2; r++) {
        int n = 2 * ty + r;
        *(float4*)&Cs[n * 132 + 4 * tx] =
            make_float4(acc[r][0] + bv.x, acc[r][1] + bv.y, acc[r][2] + bv.z, acc[r][3] + bv.w);
    }
    __syncthreads();
    // LN per node row: 8 warps x 2 rows each
    int warp = tid >> 5, lane = tid & 31;
    float4 lw = *(const float4*)&pp_lnw[lane * 4];
    float4 lb = *(const float4*)&pp_lnb[lane * 4];
#pragma unroll
    for (int r = 0; r < 2; r++) {
        int n = warp * 2 + r;
        float4 y = *(const float4*)&Cs[n * 132 + lane * 4];
        float s = y.x + y.y + y.z + y.w;
        float ss = y.x * y.x + y.y * y.y + y.z * y.z + y.w * y.w;
#pragma unroll
        for (int off = 16; off; off >>= 1) {
            s += __shfl_xor_sync(0xffffffffu, s, off);
            ss += __shfl_xor_sync(0xffffffffu, ss, off);
        }
        float mu = s * 0.0078125f;
        float var = ss * 0.0078125f - mu * mu;
        float rstd = rsqrtf(var + 1e-5f);
        float4 o = make_float4(fmaxf((y.x - mu) * rstd * lw.x + lb.x, 0.f),
                               fmaxf((y.y - mu) * rstd * lw.y + lb.y, 0.f),
                               fmaxf((y.z - mu) * rstd * lw.z + lb.z, 0.f),
                               fmaxf((y.w - mu) * rstd * lw.w + lb.w, 0.f));
        *(float4*)&g_obj[(base + n) * 128 + lane * 4] = o;
    }
}

// ---------------- batched prediction head: 16 nodes/block ----------------
__global__ __launch_bounds__(256) void predict_batched(const float* __restrict__ pr_b0,
                                                       const float* __restrict__ pr_b1,
                                                       float* __restrict__ out) {
    __shared__ float Xs[128 * 21];
    __shared__ float Hs[128 * 21];
    int base = blockIdx.x * 16;
    int tid = threadIdx.x;
    for (int idx = tid; idx < 16 * 128; idx += 256) {
        int n = idx >> 7, k = idx & 127;
        Xs[k * 21 + n] = g_obj[(base + n) * 128 + k];
    }
    __syncthreads();
    // layer1: 128 -> 128, relu, output transposed [f][n]
    {
        int tx = tid & 31, ty = tid >> 5;
        float acc[2][4];
#pragma unroll
        for (int r = 0; r < 2; r++)
#pragma unroll
            for (int c = 0; c < 4; c++) acc[r][c] = 0.f;
#pragma unroll 4
        for (int k = 0; k < 128; k++) {
            float a0 = Xs[k * 21 + 2 * ty];
            float a1 = Xs[k * 21 + 2 * ty + 1];
            float4 w = *(const float4*)&g_prw0t[k * 128 + 4 * tx];
            acc[0][0] += a0 * w.x; acc[0][1] += a0 * w.y; acc[0][2] += a0 * w.z; acc[0][3] += a0 * w.w;
            acc[1][0] += a1 * w.x; acc[1][1] += a1 * w.y; acc[1][2] += a1 * w.z; acc[1][3] += a1 * w.w;
        }
        float4 bv = *(const float4*)&pr_b0[4 * tx];
        float bb[4] = {bv.x, bv.y, bv.z, bv.w};
#pragma unroll
        for (int r = 0; r < 2; r++) {
            int n = 2 * ty + r;
#pragma unroll
            for (int c = 0; c < 4; c++)
                Hs[(4 * tx + c) * 21 + n] = fmaxf(acc[r][c] + bb[c], 0.f);
        }
    }
    __syncthreads();
    // layer2: 128 -> 32, tanh
    {
        int tx = tid & 15, ty = tid >> 4;  // f = 2tx, n = ty
        float acc0 = 0.f, acc1 = 0.f;
#pragma unroll 4
        for (int k = 0; k < 128; k++) {
            float a = Hs[k * 21 + ty];
            float2 w = *(const float2*)&g_prw1t[k * 32 + 2 * tx];
            acc0 += a * w.x;
            acc1 += a * w.y;
        }
        float2 bv = *(const float2*)&pr_b1[2 * tx];
        out[(base + ty) * 32 + 2 * tx]     = tanhf(acc0 + bv.x);
        out[(base + ty) * 32 + 2 * tx + 1] = tanhf(acc1 + bv.y);
    }
}

// ---------------- launch ----------------
extern "C" void kernel_launch(void* const* d_in, const int* in_sizes, int n_in,
                              void* d_out, int out_size) {
    const float* attrs     = (const float*)d_in[0];
    const float* states    = (const float*)d_in[1];
    const float* rel_attrs = (const float*)d_in[3];
    const float* oe_w0 = (const float*)d_in[4];
    const float* oe_b0 = (const float*)d_in[5];
    const float* oe_w1 = (const float*)d_in[6];
    const float* oe_b1 = (const float*)d_in[7];
    const float* re_w0 = (const float*)d_in[8];
    const float* re_b0 = (const float*)d_in[9];
    const float* re_w1 = (const float*)d_in[10];
    const float* re_b1 = (const float*)d_in[11];
    const float* rp_w  = (const float*)d_in[12];
    const float* rp_b  = (const float*)d_in[13];
    const float* rp_lnw = (const float*)d_in[14];
    const float* rp_lnb = (const float*)d_in[15];
    const float* pp_w  = (const float*)d_in[16];
    const float* pp_b  = (const float*)d_in[17];
    const float* pp_lnw = (const float*)d_in[18];
    const float* pp_lnb = (const float*)d_in[19];
    const float* pr_w0 = (const float*)d_in[20];
    const float* pr_b0 = (const float*)d_in[21];
    const float* pr_w1 = (const float*)d_in[22];
    const float* pr_b1 = (const float*)d_in[23];
    float* out = (float*)d_out;

    prep_kernel<<<7, 256>>>(oe_w1, re_w1, rp_w, pp_w, pr_w0, pr_w1);
    node_pre_kernel<<<NNODES, 128>>>(attrs, states, re_w0, re_b0);
    encode_batched<<<128, 256>>>(attrs, states, oe_w0, oe_b0, oe_b1);
    rel_fused_kernel<<<NNODES, 128>>>(rel_attrs, re_w0, re_b1);
    for (int step = 0; step < 2; step++) {
        rs_batched<<<128, 256>>>(rp_b);
        edge_apply_kernel<<<NNODES, 128>>>(rp_lnw, rp_lnb);
        obj_update_batched<<<128, 256>>>(pp_b, pp_lnw, pp_lnb);
    }
    predict_batched<<<128, 256>>>(pr_b0, pr_b1, out);
}

// round 4
// speedup vs baseline: 1.6508x; 1.6508x over previous
#include <cuda_runtime.h>
#include <math.h>

// B=32, N=64, ATTR=4, STATE=8, REL=4, GDIM=32, NF=128, pstep=2
#define NNODES 2048

// ---------------- scratch (static device memory) ----------------
__device__ float g_E[2048 * 64 * 128];     // E = W_rel @ rel_encode, [bi][j][f] (64 MB)
__device__ float g_obj[2048 * 128];
__device__ float g_u[2048 * 128];
__device__ float g_vt[32 * 128 * 64];      // [b][k][n]
__device__ float g_R[2048 * 128];
__device__ float g_S[2048 * 128];
__device__ float g_agg[2048 * 128];
// weights
__device__ float g_w1toe[128 * 128];       // oe_w1 transposed [k][f]
__device__ float g_w1k[128 * 128];         // re_w1 [f][k], tf32-rounded
__device__ float g_wrk[128 * 128];         // rp_w rel-block [f][k], tf32-rounded
__device__ float g_wrecvt[128 * 128];      // [k][f]
__device__ float g_wsendt[128 * 128];      // [k][f]
__device__ float g_ppwt[256 * 128];        // pp_w transposed [k][f]
__device__ float g_prw0t[128 * 128];
__device__ float g_prw1t[128 * 32];

__device__ __forceinline__ float to_tf32(float x) {
    float r;
    asm("cvt.rna.tf32.f32 %0, %1;" : "=f"(r) : "f"(x));
    return r;
}

#define MMA_TF32(d, a, b0v, b1v)                                              \
    asm volatile(                                                             \
        "mma.sync.aligned.m16n8k8.row.col.f32.tf32.tf32.f32 "                 \
        "{%0,%1,%2,%3}, {%4,%5,%6,%7}, {%8,%9}, {%0,%1,%2,%3};"               \
        : "+f"((d)[0]), "+f"((d)[1]), "+f"((d)[2]), "+f"((d)[3])              \
        : "r"(__float_as_uint((a)[0])), "r"(__float_as_uint((a)[1])),         \
          "r"(__float_as_uint((a)[2])), "r"(__float_as_uint((a)[3])),         \
          "r"(__float_as_uint(b0v)), "r"(__float_as_uint(b1v)))

// ---------------- weight prep ----------------
__global__ void prep_kernel(const float* __restrict__ oe_w1,
                            const float* __restrict__ re_w1,
                            const float* __restrict__ rp_w,
                            const float* __restrict__ pp_w,
                            const float* __restrict__ pr_w0,
                            const float* __restrict__ pr_w1) {
    int m = blockIdx.x;
    int t = threadIdx.x;
    if (m == 0) {
        for (int i = t; i < 128 * 128; i += 256) {
            int k = i >> 7, f = i & 127;
            g_w1toe[i] = oe_w1[f * 128 + k];
        }
    } else if (m == 1) {
        for (int i = t; i < 128 * 128; i += 256) g_w1k[i] = to_tf32(re_w1[i]);
    } else if (m == 2) {
        for (int i = t; i < 128 * 128; i += 256) {
            int f = i >> 7, k = i & 127;
            g_wrk[i] = to_tf32(rp_w[f * 384 + k]);
        }
    } else if (m == 3) {
        for (int i = t; i < 128 * 128; i += 256) {
            int k = i >> 7, f = i & 127;
            g_wrecvt[i] = rp_w[f * 384 + 128 + k];
        }
    } else if (m == 4) {
        for (int i = t; i < 128 * 128; i += 256) {
            int k = i >> 7, f = i & 127;
            g_wsendt[i] = rp_w[f * 384 + 256 + k];
        }
    } else if (m == 5) {
        for (int i = t; i < 256 * 128; i += 256) {
            int k = i >> 7, f = i & 127;
            g_ppwt[i] = pp_w[f * 256 + k];
        }
    } else if (m == 6) {
        for (int i = t; i < 128 * 128; i += 256) {
            int k = i >> 7, f = i & 127;
            g_prw0t[i] = pr_w0[f * 128 + k];
        }
    } else {
        for (int i = t; i < 128 * 32; i += 256) {
            int k = i >> 5, o = i & 31;
            g_prw1t[i] = pr_w1[o * 128 + k];
        }
    }
}

// ---------------- per-node parts of rel layer0 ----------------
__global__ void node_pre_kernel(const float* __restrict__ attrs,
                                const float* __restrict__ states,
                                const float* __restrict__ re_w0,
                                const float* __restrict__ re_b0) {
    int node = blockIdx.x;
    int f = threadIdx.x;
    __shared__ float sa[4];
    __shared__ float ss[8];
    if (f < 4) sa[f] = attrs[node * 4 + f];
    if (f >= 4 && f < 12) ss[f - 4] = states[node * 8 + (f - 4)];
    __syncthreads();
    const float* w = re_w0 + f * 20;  // [rel(4) | dstate(8) | recv_attr(4) | send_attr(4)]
    float u = re_b0[f];
    float v = 0.f;
#pragma unroll
    for (int c = 0; c < 8; c++) {
        float wc = w[4 + c];
        u += wc * ss[c];
        v -= wc * ss[c];
    }
#pragma unroll
    for (int c = 0; c < 4; c++) {
        u += w[12 + c] * sa[c];
        v += w[16 + c] * sa[c];
    }
    g_u[node * 128 + f] = u;
    int b = node >> 6, n = node & 63;
    g_vt[(b * 128 + f) * 64 + n] = v;
}

// ---------------- object encoder: 12 -> 128 -> 128, relu ----------------
__global__ void obj_encode_kernel(const float* __restrict__ attrs,
                                  const float* __restrict__ states,
                                  const float* __restrict__ oe_w0,
                                  const float* __restrict__ oe_b0,
                                  const float* __restrict__ oe_b1) {
    int node = blockIdx.x;
    int f = threadIdx.x;
    __shared__ float xs[12];
    __shared__ float hs[128];
    if (f < 4) xs[f] = attrs[node * 4 + f];
    if (f >= 4 && f < 12) xs[f] = states[node * 8 + (f - 4)];
    __syncthreads();
    const float* w = oe_w0 + f * 12;
    float h = oe_b0[f];
#pragma unroll
    for (int k = 0; k < 12; k++) h += w[k] * xs[k];
    hs[f] = fmaxf(h, 0.f);
    __syncthreads();
    float o = oe_b1[f];
#pragma unroll 16
    for (int k = 0; k < 128; k++) o += g_w1toe[k * 128 + f] * hs[k];
    g_obj[node * 128 + f] = fmaxf(o, 0.f);
}

// ---------------- fused relation encoder + edge-GEMM via tf32 mma.sync ----------------
// H[j][k]   = relu(W_rel.rel_attrs + u[k] + v_j[k])     (64x128, tf32 in smem)
// rel[j][f] = relu(b1[f] + H @ W1^T)                    (GEMM1, tensor pipe)
// E[j][f']  = rel @ Wr^T -> g_E[bi][j][f']              (GEMM2, tensor pipe)
__global__ __launch_bounds__(128, 4) void rel_fused_tc(const float* __restrict__ rel_attrs,
                                                       const float* __restrict__ re_w0,
                                                       const float* __restrict__ re_b1) {
    __shared__ float Hs[64 * 132];   // A operand [j][k], pad 132 -> bank-clean frag loads
    __shared__ float Ws[128 * 20];   // weight chunk [f][16k], pad 20 -> bank-clean
    __shared__ float Us[128];
    __shared__ float Bs[128];
    int bi = blockIdx.x, tid = threadIdx.x, b = bi >> 6;
    int lane = tid & 31, warp = tid >> 5;
    int jg = warp >> 1;   // j-half (0/1): rows 32*jg..32*jg+31
    int ng = warp & 1;    // f-half (0/1): cols 64*ng..64*ng+63
    Us[tid] = g_u[bi * 128 + tid];
    Bs[tid] = re_b1[tid];
    __syncthreads();

    // ---- build H[j][k] ----
    {
        int j = tid >> 1, h = tid & 1;
        float4 rv = *(const float4*)(rel_attrs + (bi * 64 + j) * 4);
        const float* vt = g_vt + b * 8192 + j;
#pragma unroll 4
        for (int kk = 0; kk < 64; kk++) {
            int k = h * 64 + kk;
            const float* w = re_w0 + k * 20;
            float val = Us[k] + vt[k * 64] + rv.x * w[0] + rv.y * w[1] + rv.z * w[2] + rv.w * w[3];
            Hs[j * 132 + k] = to_tf32(fmaxf(val, 0.f));
        }
    }

    float d[2][8][4];

    // ================= GEMM1: rel = relu(b1 + H @ W1^T) =================
#pragma unroll
    for (int m = 0; m < 2; m++)
#pragma unroll
        for (int n = 0; n < 8; n++)
#pragma unroll
            for (int q = 0; q < 4; q++) d[m][n][q] = 0.f;
#pragma unroll 1
    for (int c = 0; c < 8; c++) {
        __syncthreads();
        {
            const float4* src = (const float4*)(g_w1k + tid * 128 + c * 16);
            float4 v0 = src[0], v1 = src[1], v2 = src[2], v3 = src[3];
            float* dst = Ws + tid * 20;
            *(float4*)dst = v0; *(float4*)(dst + 4) = v1;
            *(float4*)(dst + 8) = v2; *(float4*)(dst + 12) = v3;
        }
        __syncthreads();
#pragma unroll
        for (int ks = 0; ks < 2; ks++) {
            int k0 = c * 16 + ks * 8;
            float a[2][4];
#pragma unroll
            for (int m = 0; m < 2; m++) {
                int r = 32 * jg + 16 * m + (lane >> 2);
                a[m][0] = Hs[r * 132 + k0 + (lane & 3)];
                a[m][1] = Hs[(r + 8) * 132 + k0 + (lane & 3)];
                a[m][2] = Hs[r * 132 + k0 + (lane & 3) + 4];
                a[m][3] = Hs[(r + 8) * 132 + k0 + (lane & 3) + 4];
            }
#pragma unroll
            for (int n = 0; n < 8; n++) {
                int f = 64 * ng + 8 * n + (lane >> 2);
                float b0 = Ws[f * 20 + ks * 8 + (lane & 3)];
                float b1 = Ws[f * 20 + ks * 8 + (lane & 3) + 4];
                MMA_TF32(d[0][n], a[0], b0, b1);
                MMA_TF32(d[1][n], a[1], b0, b1);
            }
        }
    }
    __syncthreads();  // all H reads done before rel overwrites Hs
    // epilogue 1: bias + relu + tf32-round, rel[j][f] into Hs
#pragma unroll
    for (int m = 0; m < 2; m++) {
        int r0 = 32 * jg + 16 * m + (lane >> 2);
#pragma unroll
        for (int n = 0; n < 8; n++) {
            int f0 = 64 * ng + 8 * n + 2 * (lane & 3);
            float bb0 = Bs[f0], bb1 = Bs[f0 + 1];
            Hs[r0 * 132 + f0]       = to_tf32(fmaxf(d[m][n][0] + bb0, 0.f));
            Hs[r0 * 132 + f0 + 1]   = to_tf32(fmaxf(d[m][n][1] + bb1, 0.f));
            Hs[(r0 + 8) * 132 + f0]     = to_tf32(fmaxf(d[m][n][2] + bb0, 0.f));
            Hs[(r0 + 8) * 132 + f0 + 1] = to_tf32(fmaxf(d[m][n][3] + bb1, 0.f));
        }
    }

    // ================= GEMM2: E = rel @ Wr^T =================
#pragma unroll
    for (int m = 0; m < 2; m++)
#pragma unroll
        for (int n = 0; n < 8; n++)
#pragma unroll
            for (int q = 0; q < 4; q++) d[m][n][q] = 0.f;
#pragma unroll 1
    for (int c = 0; c < 8; c++) {
        __syncthreads();  // first iter also orders epilogue-1 writes
        {
            const float4* src = (const float4*)(g_wrk + tid * 128 + c * 16);
            float4 v0 = src[0], v1 = src[1], v2 = src[2], v3 = src[3];
            float* dst = Ws + tid * 20;
            *(float4*)dst = v0; *(float4*)(dst + 4) = v1;
            *(float4*)(dst + 8) = v2; *(float4*)(dst + 12) = v3;
        }
        __syncthreads();
#pragma unroll
        for (int ks = 0; ks < 2; ks++) {
            int k0 = c * 16 + ks * 8;
            float a[2][4];
#pragma unroll
            for (int m = 0; m < 2; m++) {
                int r = 32 * jg + 16 * m + (lane >> 2);
                a[m][0] = Hs[r * 132 + k0 + (lane & 3)];
                a[m][1] = Hs[(r + 8) * 132 + k0 + (lane & 3)];
                a[m][2] = Hs[r * 132 + k0 + (lane & 3) + 4];
                a[m][3] = Hs[(r + 8) * 132 + k0 + (lane & 3) + 4];
            }
#pragma unroll
            for (int n = 0; n < 8; n++) {
                int f = 64 * ng + 8 * n + (lane >> 2);
                float b0 = Ws[f * 20 + ks * 8 + (lane & 3)];
                float b1 = Ws[f * 20 + ks * 8 + (lane & 3) + 4];
                MMA_TF32(d[0][n], a[0], b0, b1);
                MMA_TF32(d[1][n], a[1], b0, b1);
            }
        }
    }
    // epilogue 2: store E to global
    float* Ep = g_E + (long)bi * 8192;
#pragma unroll
    for (int m = 0; m < 2; m++) {
        int r0 = 32 * jg + 16 * m + (lane >> 2);
#pragma unroll
        for (int n = 0; n < 8; n++) {
            int f0 = 64 * ng + 8 * n + 2 * (lane & 3);
            *(float2*)&Ep[r0 * 128 + f0] = make_float2(d[m][n][0], d[m][n][1]);
            *(float2*)&Ep[(r0 + 8) * 128 + f0] = make_float2(d[m][n][2], d[m][n][3]);
        }
    }
}

// ---------------- R/S precompute per step ----------------
__global__ void rs_kernel(const float* __restrict__ rp_b) {
    int node = blockIdx.x;
    int f = threadIdx.x;
    __shared__ float Os[128];
    Os[f] = g_obj[node * 128 + f];
    __syncthreads();
    float r = rp_b[f], s = 0.f;
#pragma unroll 8
    for (int k = 0; k < 128; k++) {
        float o = Os[k];
        r += g_wrecvt[k * 128 + f] * o;
        s += g_wsendt[k * 128 + f] * o;
    }
    g_R[node * 128 + f] = r;
    g_S[node * 128 + f] = s;
}

// ---------------- edge apply: Y = E + R_i + S_j, LN, relu, sum over j ----------------
__global__ __launch_bounds__(128) void edge_apply_kernel(const float* __restrict__ rp_lnw,
                                                         const float* __restrict__ rp_lnb) {
    __shared__ float Rs[128];
    __shared__ float Ps[512];
    int bi = blockIdx.x;
    int tid = threadIdx.x;
    int b = bi >> 6;
    int warp = tid >> 5, lane = tid & 31;
    Rs[tid] = g_R[bi * 128 + tid];
    __syncthreads();
    float4 rv = *(const float4*)&Rs[lane * 4];
    float4 lw = *(const float4*)&rp_lnw[lane * 4];
    float4 lb = *(const float4*)&rp_lnb[lane * 4];
    const float* Ep = g_E + (long)bi * 8192;
    float ag0 = 0.f, ag1 = 0.f, ag2 = 0.f, ag3 = 0.f;
#pragma unroll 4
    for (int r = 0; r < 16; r++) {
        int j = warp * 16 + r;
        float4 e = *(const float4*)&Ep[j * 128 + lane * 4];
        float4 sv = *(const float4*)&g_S[(b * 64 + j) * 128 + lane * 4];
        float4 y = make_float4(e.x + rv.x + sv.x, e.y + rv.y + sv.y,
                               e.z + rv.z + sv.z, e.w + rv.w + sv.w);
        float s = y.x + y.y + y.z + y.w;
        float ss = y.x * y.x + y.y * y.y + y.z * y.z + y.w * y.w;
#pragma unroll
        for (int off = 16; off; off >>= 1) {
            s += __shfl_xor_sync(0xffffffffu, s, off);
            ss += __shfl_xor_sync(0xffffffffu, ss, off);
        }
        float mu = s * 0.0078125f;
        float var = ss * 0.0078125f - mu * mu;
        float rstd = rsqrtf(var + 1e-5f);
        ag0 += fmaxf((y.x - mu) * rstd * lw.x + lb.x, 0.f);
        ag1 += fmaxf((y.y - mu) * rstd * lw.y + lb.y, 0.f);
        ag2 += fmaxf((y.z - mu) * rstd * lw.z + lb.z, 0.f);
        ag3 += fmaxf((y.w - mu) * rstd * lw.w + lb.w, 0.f);
    }
    *(float4*)&Ps[warp * 128 + lane * 4] = make_float4(ag0, ag1, ag2, ag3);
    __syncthreads();
    g_agg[bi * 128 + tid] = Ps[tid] + Ps[128 + tid] + Ps[256 + tid] + Ps[384 + tid];
}

// ---------------- object update: [obj|agg](256) -> 128, LN, relu ----------------
__global__ void obj_update_kernel(const float* __restrict__ pp_b,
                                  const float* __restrict__ pp_lnw,
                                  const float* __restrict__ pp_lnb) {
    int node = blockIdx.x;
    int f = threadIdx.x;
    __shared__ float Xs[256];
    __shared__ float rs_[4], rss_[4];
    Xs[f] = g_obj[node * 128 + f];
    Xs[128 + f] = g_agg[node * 128 + f];
    __syncthreads();
    float acc = pp_b[f];
#pragma unroll 8
    for (int k = 0; k < 256; k++) acc += g_ppwt[k * 128 + f] * Xs[k];
    float s = acc, ss = acc * acc;
#pragma unroll
    for (int off = 16; off; off >>= 1) {
        s += __shfl_xor_sync(0xffffffffu, s, off);
        ss += __shfl_xor_sync(0xffffffffu, ss, off);
    }
    int warp = f >> 5, lane = f & 31;
    if (lane == 0) { rs_[warp] = s; rss_[warp] = ss; }
    __syncthreads();
    s = rs_[0] + rs_[1] + rs_[2] + rs_[3];
    ss = rss_[0] + rss_[1] + rss_[2] + rss_[3];
    float mu = s * 0.0078125f;
    float var = ss * 0.0078125f - mu * mu;
    float y = (acc - mu) * rsqrtf(var + 1e-5f) * pp_lnw[f] + pp_lnb[f];
    g_obj[node * 128 + f] = fmaxf(y, 0.f);
}

// ---------------- prediction head: 128 -> relu -> 32 -> tanh ----------------
__global__ void predict_kernel(const float* __restrict__ pr_b0,
                               const float* __restrict__ pr_b1,
                               float* __restrict__ out) {
    int node = blockIdx.x;
    int f = threadIdx.x;
    __shared__ float Os[128];
    __shared__ float Hss[128];
    Os[f] = g_obj[node * 128 + f];
    __syncthreads();
    float h = pr_b0[f];
#pragma unroll 8
    for (int k = 0; k < 128; k++) h += g_prw0t[k * 128 + f] * Os[k];
    Hss[f] = fmaxf(h, 0.f);
    __syncthreads();
    if (f < 32) {
        float o = pr_b1[f];
#pragma unroll 8
        for (int k = 0; k < 128; k++) o += g_prw1t[k * 32 + f] * Hss[k];
        out[node * 32 + f] = tanhf(o);
    }
}

// ---------------- launch ----------------
extern "C" void kernel_launch(void* const* d_in, const int* in_sizes, int n_in,
                              void* d_out, int out_size) {
    const float* attrs     = (const float*)d_in[0];
    const float* states    = (const float*)d_in[1];
    const float* rel_attrs = (const float*)d_in[3];
    const float* oe_w0 = (const float*)d_in[4];
    const float* oe_b0 = (const float*)d_in[5];
    const float* oe_w1 = (const float*)d_in[6];
    const float* oe_b1 = (const float*)d_in[7];
    const float* re_w0 = (const float*)d_in[8];
    const float* re_b0 = (const float*)d_in[9];
    const float* re_w1 = (const float*)d_in[10];
    const float* re_b1 = (const float*)d_in[11];
    const float* rp_w  = (const float*)d_in[12];
    const float* rp_b  = (const float*)d_in[13];
    const float* rp_lnw = (const float*)d_in[14];
    const float* rp_lnb = (const float*)d_in[15];
    const float* pp_w  = (const float*)d_in[16];
    const float* pp_b  = (const float*)d_in[17];
    const float* pp_lnw = (const float*)d_in[18];
    const float* pp_lnb = (const float*)d_in[19];
    const float* pr_w0 = (const float*)d_in[20];
    const float* pr_b0 = (const float*)d_in[21];
    const float* pr_w1 = (const float*)d_in[22];
    const float* pr_b1 = (const float*)d_in[23];
    float* out = (float*)d_out;

    prep_kernel<<<8, 256>>>(oe_w1, re_w1, rp_w, pp_w, pr_w0, pr_w1);
    node_pre_kernel<<<NNODES, 128>>>(attrs, states, re_w0, re_b0);
    obj_encode_kernel<<<NNODES, 128>>>(attrs, states, oe_w0, oe_b0, oe_b1);
    rel_fused_tc<<<NNODES, 128>>>(rel_attrs, re_w0, re_b1);
    for (int step = 0; step < 2; step++) {
        rs_kernel<<<NNODES, 128>>>(rp_b);
        edge_apply_kernel<<<NNODES, 128>>>(rp_lnw, rp_lnb);
        obj_update_kernel<<<NNODES, 128>>>(pp_b, pp_lnw, pp_lnb);
    }
    predict_kernel<<<NNODES, 128>>>(pr_b0, pr_b1, out);
}

// round 6
// speedup vs baseline: 1.8527x; 1.1223x over previous
#include <cuda_runtime.h>
#include <stdint.h>
#include <math.h>

// B=32, N=64, ATTR=4, STATE=8, REL=4, GDIM=32, NF=128, pstep=2
#define NNODES 2048

// ---------------- scratch (static device memory) ----------------
__device__ float g_E[2048 * 64 * 128];     // E = W_rel @ rel_encode, [bi][j][f] (64 MB)
__device__ float g_obj[2048 * 128];
__device__ float g_u[2048 * 128];
__device__ float g_vt[32 * 128 * 64];      // [b][k][n]
__device__ float g_R[2048 * 128];
__device__ float g_S[2048 * 128];
__device__ float g_agg[2048 * 128];
__device__ float g_w1k[128 * 128];         // re_w1 [f][k], tf32-rounded
__device__ float g_wrk[128 * 128];         // rp_w rel-block [f][k], tf32-rounded

__device__ __forceinline__ float to_tf32(float x) {
    float r;
    asm("cvt.rna.tf32.f32 %0, %1;" : "=f"(r) : "f"(x));
    return r;
}

#define LDSM_X4(r, addr)                                                      \
    asm volatile("ldmatrix.sync.aligned.m8n8.x4.shared.b16 {%0,%1,%2,%3}, [%4];" \
                 : "=r"((r)[0]), "=r"((r)[1]), "=r"((r)[2]), "=r"((r)[3])     \
                 : "r"(addr))

#define MMA_TF32(d, a, b0v, b1v)                                              \
    asm volatile(                                                             \
        "mma.sync.aligned.m16n8k8.row.col.f32.tf32.tf32.f32 "                 \
        "{%0,%1,%2,%3}, {%4,%5,%6,%7}, {%8,%9}, {%0,%1,%2,%3};"               \
        : "+f"((d)[0]), "+f"((d)[1]), "+f"((d)[2]), "+f"((d)[3])              \
        : "r"((a)[0]), "r"((a)[1]), "r"((a)[2]), "r"((a)[3]),                 \
          "r"(b0v), "r"(b1v))

// ---------------- weight prep: tf32 rounding of the two MMA weights ----------------
__global__ void prep_kernel(const float* __restrict__ re_w1,
                            const float* __restrict__ rp_w) {
    int m = blockIdx.x;
    int t = threadIdx.x;
    if (m == 0) {
        for (int i = t; i < 128 * 128; i += 256) g_w1k[i] = to_tf32(re_w1[i]);
    } else {
        for (int i = t; i < 128 * 128; i += 256) {
            int f = i >> 7, k = i & 127;
            g_wrk[i] = to_tf32(rp_w[f * 384 + k]);
        }
    }
}

// ---------------- per-node parts of rel layer0 ----------------
__global__ void node_pre_kernel(const float* __restrict__ attrs,
                                const float* __restrict__ states,
                                const float* __restrict__ re_w0,
                                const float* __restrict__ re_b0) {
    int node = blockIdx.x;
    int f = threadIdx.x;
    __shared__ float sa[4];
    __shared__ float ss[8];
    if (f < 4) sa[f] = attrs[node * 4 + f];
    if (f >= 4 && f < 12) ss[f - 4] = states[node * 8 + (f - 4)];
    __syncthreads();
    const float* w = re_w0 + f * 20;
    float u = re_b0[f];
    float v = 0.f;
#pragma unroll
    for (int c = 0; c < 8; c++) {
        float wc = w[4 + c];
        u += wc * ss[c];
        v -= wc * ss[c];
    }
#pragma unroll
    for (int c = 0; c < 4; c++) {
        u += w[12 + c] * sa[c];
        v += w[16 + c] * sa[c];
    }
    g_u[node * 128 + f] = u;
    int b = node >> 6, n = node & 63;
    g_vt[(b * 128 + f) * 64 + n] = v;
}

// ---------------- object encoder: 8 nodes/block ----------------
__global__ __launch_bounds__(128) void obj_encode_v2(const float* __restrict__ attrs,
                                                     const float* __restrict__ states,
                                                     const float* __restrict__ oe_w0,
                                                     const float* __restrict__ oe_b0,
                                                     const float* __restrict__ oe_w1,
                                                     const float* __restrict__ oe_b1) {
    __shared__ float xs[8][12];
    __shared__ float Hs1[8][128];
    int base = blockIdx.x * 8;
    int f = threadIdx.x;
    if (f < 96) {
        int n = f / 12, c = f % 12;
        xs[n][c] = (c < 4) ? attrs[(base + n) * 4 + c] : states[(base + n) * 8 + (c - 4)];
    }
    __syncthreads();
    float w0r[12];
#pragma unroll
    for (int c = 0; c < 12; c++) w0r[c] = oe_w0[f * 12 + c];
    float b0 = oe_b0[f];
#pragma unroll
    for (int n = 0; n < 8; n++) {
        float h = b0;
#pragma unroll
        for (int c = 0; c < 12; c++) h += w0r[c] * xs[n][c];
        Hs1[n][f] = fmaxf(h, 0.f);
    }
    __syncthreads();
    float acc[8] = {0, 0, 0, 0, 0, 0, 0, 0};
#pragma unroll 4
    for (int k = 0; k < 128; k += 4) {
        float4 w = *(const float4*)&oe_w1[f * 128 + k];
#pragma unroll
        for (int n = 0; n < 8; n++) {
            float4 x = *(const float4*)&Hs1[n][k];
            acc[n] += w.x * x.x + w.y * x.y + w.z * x.z + w.w * x.w;
        }
    }
    float b1 = oe_b1[f];
#pragma unroll
    for (int n = 0; n < 8; n++)
        g_obj[(base + n) * 128 + f] = fmaxf(acc[n] + b1, 0.f);
}

// ---------------- fused relation encoder + edge-GEMM via tf32 mma + ldmatrix ----------------
__global__ __launch_bounds__(128) void rel_fused_tc(const float* __restrict__ rel_attrs,
                                                    const float* __restrict__ re_w0,
                                                    const float* __restrict__ re_b1) {
    extern __shared__ float dsm[];
    float* Hs = dsm;                    // 64 x 132
    float* Wsm = dsm + 8448;            // 128 x 132
    float* Us = dsm + 8448 + 16896;     // 128
    float* Bs = Us + 128;               // 128
    int bi = blockIdx.x, tid = threadIdx.x, b = bi >> 6;
    int lane = tid & 31, warp = tid >> 5;
    int jg = warp >> 1;   // j-half: rows 32*jg..+31
    int ng = warp & 1;    // f-half: cols 64*ng..+63
    uint32_t hs_base = (uint32_t)__cvta_generic_to_shared(Hs);
    uint32_t w_base = (uint32_t)__cvta_generic_to_shared(Wsm);

    Us[tid] = g_u[bi * 128 + tid];
    Bs[tid] = re_b1[tid];
    // load W1 (coalesced) into smem [f][k] stride 132
#pragma unroll 8
    for (int i = 0; i < 32; i++) {
        int idx = (i * 128 + tid) * 4;
        float4 v = *(const float4*)&g_w1k[idx];
        *(float4*)&Wsm[(idx >> 7) * 132 + (idx & 127)] = v;
    }
    __syncthreads();

    // ---- build H[j][k] (tf32) ----
    {
        int j = tid >> 1, h = tid & 1;
        float4 rv = *(const float4*)(rel_attrs + (bi * 64 + j) * 4);
        const float* vt = g_vt + b * 8192 + j;
#pragma unroll 4
        for (int kk = 0; kk < 64; kk++) {
            int k = h * 64 + kk;
            const float* w = re_w0 + k * 20;
            float val = Us[k] + vt[k * 64] + rv.x * w[0] + rv.y * w[1] + rv.z * w[2] + rv.w * w[3];
            Hs[j * 132 + k] = to_tf32(fmaxf(val, 0.f));
        }
    }
    __syncthreads();

    // ldmatrix address components
    uint32_t aAddr = hs_base + 4 * ((32 * jg + (lane & 15)) * 132 + 4 * (lane >> 4));
    uint32_t bAddr = w_base + 4 * ((64 * ng + (lane & 7)) * 132 + 4 * (lane >> 3));
    float d[2][8][4];

    // ================= GEMM1: rel = relu(b1 + H @ W1^T) =================
#pragma unroll
    for (int m = 0; m < 2; m++)
#pragma unroll
        for (int n = 0; n < 8; n++)
#pragma unroll
            for (int q = 0; q < 4; q++) d[m][n][q] = 0.f;
#pragma unroll
    for (int c = 0; c < 8; c++) {
        int k0 = c * 16;
        uint32_t a[2][2][4];
#pragma unroll
        for (int m = 0; m < 2; m++)
#pragma unroll
            for (int s = 0; s < 2; s++)
                LDSM_X4(a[m][s], aAddr + 4 * (m * 16 * 132 + k0 + 8 * s));
        uint32_t bb[8][4];
#pragma unroll
        for (int n = 0; n < 8; n++)
            LDSM_X4(bb[n], bAddr + 4 * (n * 8 * 132 + k0));
#pragma unroll
        for (int s = 0; s < 2; s++)
#pragma unroll
            for (int n = 0; n < 8; n++) {
                MMA_TF32(d[0][n], a[0][s], bb[n][2 * s], bb[n][2 * s + 1]);
                MMA_TF32(d[1][n], a[1][s], bb[n][2 * s], bb[n][2 * s + 1]);
            }
    }
    __syncthreads();  // all Hs / Wsm reads of GEMM1 complete

    // epilogue 1: bias + relu + tf32, rel[j][f] into Hs; also load Wr into Wsm
#pragma unroll
    for (int m = 0; m < 2; m++) {
        int r0 = 32 * jg + 16 * m + (lane >> 2);
#pragma unroll
        for (int n = 0; n < 8; n++) {
            int f0 = 64 * ng + 8 * n + 2 * (lane & 3);
            float bb0 = Bs[f0], bb1 = Bs[f0 + 1];
            Hs[r0 * 132 + f0]           = to_tf32(fmaxf(d[m][n][0] + bb0, 0.f));
            Hs[r0 * 132 + f0 + 1]       = to_tf32(fmaxf(d[m][n][1] + bb1, 0.f));
            Hs[(r0 + 8) * 132 + f0]     = to_tf32(fmaxf(d[m][n][2] + bb0, 0.f));
            Hs[(r0 + 8) * 132 + f0 + 1] = to_tf32(fmaxf(d[m][n][3] + bb1, 0.f));
        }
    }
#pragma unroll 8
    for (int i = 0; i < 32; i++) {
        int idx = (i * 128 + tid) * 4;
        float4 v = *(const float4*)&g_wrk[idx];
        *(float4*)&Wsm[(idx >> 7) * 132 + (idx & 127)] = v;
    }
    __syncthreads();

    // ================= GEMM2: E = rel @ Wr^T =================
#pragma unroll
    for (int m = 0; m < 2; m++)
#pragma unroll
        for (int n = 0; n < 8; n++)
#pragma unroll
            for (int q = 0; q < 4; q++) d[m][n][q] = 0.f;
#pragma unroll
    for (int c = 0; c < 8; c++) {
        int k0 = c * 16;
        uint32_t a[2][2][4];
#pragma unroll
        for (int m = 0; m < 2; m++)
#pragma unroll
            for (int s = 0; s < 2; s++)
                LDSM_X4(a[m][s], aAddr + 4 * (m * 16 * 132 + k0 + 8 * s));
        uint32_t bb[8][4];
#pragma unroll
        for (int n = 0; n < 8; n++)
            LDSM_X4(bb[n], bAddr + 4 * (n * 8 * 132 + k0));
#pragma unroll
        for (int s = 0; s < 2; s++)
#pragma unroll
            for (int n = 0; n < 8; n++) {
                MMA_TF32(d[0][n], a[0][s], bb[n][2 * s], bb[n][2 * s + 1]);
                MMA_TF32(d[1][n], a[1][s], bb[n][2 * s], bb[n][2 * s + 1]);
            }
    }
    // epilogue 2: store E
    float* Ep = g_E + (long)bi * 8192;
#pragma unroll
    for (int m = 0; m < 2; m++) {
        int r0 = 32 * jg + 16 * m + (lane >> 2);
#pragma unroll
        for (int n = 0; n < 8; n++) {
            int f0 = 64 * ng + 8 * n + 2 * (lane & 3);
            *(float2*)&Ep[r0 * 128 + f0] = make_float2(d[m][n][0], d[m][n][1]);
            *(float2*)&Ep[(r0 + 8) * 128 + f0] = make_float2(d[m][n][2], d[m][n][3]);
        }
    }
}

// ---------------- R/S precompute: 8 nodes/block ----------------
__global__ __launch_bounds__(128) void rs_v2(const float* __restrict__ rp_w,
                                             const float* __restrict__ rp_b) {
    __shared__ float Os[8][128];
    int base = blockIdx.x * 8;
    int f = threadIdx.x;
#pragma unroll
    for (int n = 0; n < 8; n++) Os[n][f] = g_obj[(base + n) * 128 + f];
    __syncthreads();
    float r[8] = {0, 0, 0, 0, 0, 0, 0, 0};
    float s[8] = {0, 0, 0, 0, 0, 0, 0, 0};
    const float* wrow = rp_w + f * 384;
#pragma unroll 4
    for (int k = 0; k < 128; k += 4) {
        float4 wr = *(const float4*)&wrow[128 + k];
        float4 ws = *(const float4*)&wrow[256 + k];
#pragma unroll
        for (int n = 0; n < 8; n++) {
            float4 o = *(const float4*)&Os[n][k];
            r[n] += wr.x * o.x + wr.y * o.y + wr.z * o.z + wr.w * o.w;
            s[n] += ws.x * o.x + ws.y * o.y + ws.z * o.z + ws.w * o.w;
        }
    }
    float bb = rp_b[f];
#pragma unroll
    for (int n = 0; n < 8; n++) {
        g_R[(base + n) * 128 + f] = r[n] + bb;
        g_S[(base + n) * 128 + f] = s[n];
    }
}

// ---------------- edge apply: Y = E + R_i + S_j, LN, relu, sum over j ----------------
__global__ __launch_bounds__(128) void edge_apply_kernel(const float* __restrict__ rp_lnw,
                                                         const float* __restrict__ rp_lnb) {
    __shared__ float Rs[128];
    __shared__ float Ps[512];
    int bi = blockIdx.x;
    int tid = threadIdx.x;
    int b = bi >> 6;
    int warp = tid >> 5, lane = tid & 31;
    Rs[tid] = g_R[bi * 128 + tid];
    __syncthreads();
    float4 rv = *(const float4*)&Rs[lane * 4];
    float4 lw = *(const float4*)&rp_lnw[lane * 4];
    float4 lb = *(const float4*)&rp_lnb[lane * 4];
    const float* Ep = g_E + (long)bi * 8192;
    float ag0 = 0.f, ag1 = 0.f, ag2 = 0.f, ag3 = 0.f;
#pragma unroll 4
    for (int r = 0; r < 16; r++) {
        int j = warp * 16 + r;
        float4 e = *(const float4*)&Ep[j * 128 + lane * 4];
        float4 sv = *(const float4*)&g_S[(b * 64 + j) * 128 + lane * 4];
        float4 y = make_float4(e.x + rv.x + sv.x, e.y + rv.y + sv.y,
                               e.z + rv.z + sv.z, e.w + rv.w + sv.w);
        float s = y.x + y.y + y.z + y.w;
        float ss = y.x * y.x + y.y * y.y + y.z * y.z + y.w * y.w;
#pragma unroll
        for (int off = 16; off; off >>= 1) {
            s += __shfl_xor_sync(0xffffffffu, s, off);
            ss += __shfl_xor_sync(0xffffffffu, ss, off);
        }
        float mu = s * 0.0078125f;
        float var = ss * 0.0078125f - mu * mu;
        float rstd = rsqrtf(var + 1e-5f);
        ag0 += fmaxf((y.x - mu) * rstd * lw.x + lb.x, 0.f);
        ag1 += fmaxf((y.y - mu) * rstd * lw.y + lb.y, 0.f);
        ag2 += fmaxf((y.z - mu) * rstd * lw.z + lb.z, 0.f);
        ag3 += fmaxf((y.w - mu) * rstd * lw.w + lb.w, 0.f);
    }
    *(float4*)&Ps[warp * 128 + lane * 4] = make_float4(ag0, ag1, ag2, ag3);
    __syncthreads();
    g_agg[bi * 128 + tid] = Ps[tid] + Ps[128 + tid] + Ps[256 + tid] + Ps[384 + tid];
}

// ---------------- object update: 8 nodes/block ----------------
__global__ __launch_bounds__(128) void obj_update_v2(const float* __restrict__ pp_w,
                                                     const float* __restrict__ pp_b,
                                                     const float* __restrict__ pp_lnw,
                                                     const float* __restrict__ pp_lnb) {
    __shared__ float Xs[8][256];
    __shared__ float Cs[8][132];
    int base = blockIdx.x * 8;
    int f = threadIdx.x;
#pragma unroll
    for (int n = 0; n < 8; n++) {
        Xs[n][f] = g_obj[(base + n) * 128 + f];
        Xs[n][128 + f] = g_agg[(base + n) * 128 + f];
    }
    __syncthreads();
    float acc[8] = {0, 0, 0, 0, 0, 0, 0, 0};
    const float* wrow = pp_w + f * 256;
#pragma unroll 4
    for (int k = 0; k < 256; k += 4) {
        float4 w = *(const float4*)&wrow[k];
#pragma unroll
        for (int n = 0; n < 8; n++) {
            float4 x = *(const float4*)&Xs[n][k];
            acc[n] += w.x * x.x + w.y * x.y + w.z * x.z + w.w * x.w;
        }
    }
    float bb = pp_b[f];
#pragma unroll
    for (int n = 0; n < 8; n++) Cs[n][f] = acc[n] + bb;
    __syncthreads();
    int warp = f >> 5, lane = f & 31;
    float4 lw = *(const float4*)&pp_lnw[lane * 4];
    float4 lb = *(const float4*)&pp_lnb[lane * 4];
#pragma unroll
    for (int r = 0; r < 2; r++) {
        int n = warp * 2 + r;
        float4 y = *(const float4*)&Cs[n][lane * 4];
        float s = y.x + y.y + y.z + y.w;
        float ss = y.x * y.x + y.y * y.y + y.z * y.z + y.w * y.w;
#pragma unroll
        for (int off = 16; off; off >>= 1) {
            s += __shfl_xor_sync(0xffffffffu, s, off);
            ss += __shfl_xor_sync(0xffffffffu, ss, off);
        }
        float mu = s * 0.0078125f;
        float var = ss * 0.0078125f - mu * mu;
        float rstd = rsqrtf(var + 1e-5f);
        float4 o = make_float4(fmaxf((y.x - mu) * rstd * lw.x + lb.x, 0.f),
                               fmaxf((y.y - mu) * rstd * lw.y + lb.y, 0.f),
                               fmaxf((y.z - mu) * rstd * lw.z + lb.z, 0.f),
                               fmaxf((y.w - mu) * rstd * lw.w + lb.w, 0.f));
        *(float4*)&g_obj[(base + n) * 128 + lane * 4] = o;
    }
}

// ---------------- prediction head: 8 nodes/block ----------------
__global__ __launch_bounds__(128) void predict_v2(const float* __restrict__ pr_w0,
                                                  const float* __restrict__ pr_b0,
                                                  const float* __restrict__ pr_w1,
                                                  const float* __restrict__ pr_b1,
                                                  float* __restrict__ out) {
    __shared__ float Xs[8][128];
    __shared__ float Hs2[8][128];
    int base = blockIdx.x * 8;
    int f = threadIdx.x;
#pragma unroll
    for (int n = 0; n < 8; n++) Xs[n][f] = g_obj[(base + n) * 128 + f];
    __syncthreads();
    float acc[8] = {0, 0, 0, 0, 0, 0, 0, 0};
    const float* wrow = pr_w0 + f * 128;
#pragma unroll 4
    for (int k = 0; k < 128; k += 4) {
        float4 w = *(const float4*)&wrow[k];
#pragma unroll
        for (int n = 0; n < 8; n++) {
            float4 x = *(const float4*)&Xs[n][k];
            acc[n] += w.x * x.x + w.y * x.y + w.z * x.z + w.w * x.w;
        }
    }
    float b0 = pr_b0[f];
#pragma unroll
    for (int n = 0; n < 8; n++) Hs2[n][f] = fmaxf(acc[n] + b0, 0.f);
    __syncthreads();
    // layer2: 8 nodes x 32 outs = 256 outputs, 2 per thread
    int n = f >> 4, op = f & 15;
    float a0 = 0.f, a1 = 0.f;
    const float* w0p = pr_w1 + (2 * op) * 128;
    const float* w1p = pr_w1 + (2 * op + 1) * 128;
#pragma unroll 4
    for (int k = 0; k < 128; k += 4) {
        float4 x = *(const float4*)&Hs2[n][k];
        float4 wa = *(const float4*)&w0p[k];
        float4 wb = *(const float4*)&w1p[k];
        a0 += wa.x * x.x + wa.y * x.y + wa.z * x.z + wa.w * x.w;
        a1 += wb.x * x.x + wb.y * x.y + wb.z * x.z + wb.w * x.w;
    }
    out[(base + n) * 32 + 2 * op]     = tanhf(a0 + pr_b1[2 * op]);
    out[(base + n) * 32 + 2 * op + 1] = tanhf(a1 + pr_b1[2 * op + 1]);
}

// ---------------- launch ----------------
extern "C" void kernel_launch(void* const* d_in, const int* in_sizes, int n_in,
                              void* d_out, int out_size) {
    const float* attrs     = (const float*)d_in[0];
    const float* states    = (const float*)d_in[1];
    const float* rel_attrs = (const float*)d_in[3];
    const float* oe_w0 = (const float*)d_in[4];
    const float* oe_b0 = (const float*)d_in[5];
    const float* oe_w1 = (const float*)d_in[6];
    const float* oe_b1 = (const float*)d_in[7];
    const float* re_w0 = (const float*)d_in[8];
    const float* re_b0 = (const float*)d_in[9];
    const float* re_w1 = (const float*)d_in[10];
    const float* re_b1 = (const float*)d_in[11];
    const float* rp_w  = (const float*)d_in[12];
    const float* rp_b  = (const float*)d_in[13];
    const float* rp_lnw = (const float*)d_in[14];
    const float* rp_lnb = (const float*)d_in[15];
    const float* pp_w  = (const float*)d_in[16];
    const float* pp_b  = (const float*)d_in[17];
    const float* pp_lnw = (const float*)d_in[18];
    const float* pp_lnb = (const float*)d_in[19];
    const float* pr_w0 = (const float*)d_in[20];
    const float* pr_b0 = (const float*)d_in[21];
    const float* pr_w1 = (const float*)d_in[22];
    const float* pr_b1 = (const float*)d_in[23];
    float* out = (float*)d_out;

    const int dsm_bytes = (8448 + 16896 + 256) * 4;  // ~102.4 KB
    cudaFuncSetAttribute(rel_fused_tc, cudaFuncAttributeMaxDynamicSharedMemorySize, dsm_bytes);

    prep_kernel<<<2, 256>>>(re_w1, rp_w);
    node_pre_kernel<<<NNODES, 128>>>(attrs, states, re_w0, re_b0);
    obj_encode_v2<<<256, 128>>>(attrs, states, oe_w0, oe_b0, oe_w1, oe_b1);
    rel_fused_tc<<<NNODES, 128, dsm_bytes>>>(rel_attrs, re_w0, re_b1);
    for (int step = 0; step < 2; step++) {
        rs_v2<<<256, 128>>>(rp_w, rp_b);
        edge_apply_kernel<<<NNODES, 128>>>(rp_lnw, rp_lnb);
        obj_update_v2<<<256, 128>>>(pp_w, pp_b, pp_lnw, pp_lnb);
    }
    predict_v2<<<256, 128>>>(pr_w0, pr_b0, pr_w1, pr_b1, out);
}

// round 7
// speedup vs baseline: 2.0827x; 1.1242x over previous
#include <cuda_runtime.h>
#include <stdint.h>
#include <math.h>

// B=32, N=64, ATTR=4, STATE=8, REL=4, GDIM=32, NF=128, pstep=2
#define NNODES 2048

// ---------------- scratch (static device memory) ----------------
__device__ float g_E[2048 * 64 * 128];     // E = W_rel @ rel_encode, [bi][j][f] (64 MB)
__device__ float g_obj[2048 * 128];
__device__ float g_u[2048 * 128];
__device__ float g_vt[32 * 128 * 64];      // [b][k][n]
__device__ float g_R[2048 * 128];
__device__ float g_S[2048 * 128];
__device__ float g_agg[2048 * 128];
__device__ float g_w1k[128 * 128];         // re_w1 [f][k], tf32-rounded
__device__ float g_wrk[128 * 128];         // rp_w rel-block [f][k], tf32-rounded

__device__ __forceinline__ float to_tf32(float x) {
    float r;
    asm("cvt.rna.tf32.f32 %0, %1;" : "=f"(r) : "f"(x));
    return r;
}

#define LDSM_X4(r, addr)                                                      \
    asm volatile("ldmatrix.sync.aligned.m8n8.x4.shared.b16 {%0,%1,%2,%3}, [%4];" \
                 : "=r"((r)[0]), "=r"((r)[1]), "=r"((r)[2]), "=r"((r)[3])     \
                 : "r"(addr))

#define MMA_TF32(d, a, b0v, b1v)                                              \
    asm volatile(                                                             \
        "mma.sync.aligned.m16n8k8.row.col.f32.tf32.tf32.f32 "                 \
        "{%0,%1,%2,%3}, {%4,%5,%6,%7}, {%8,%9}, {%0,%1,%2,%3};"               \
        : "+f"((d)[0]), "+f"((d)[1]), "+f"((d)[2]), "+f"((d)[3])              \
        : "r"((a)[0]), "r"((a)[1]), "r"((a)[2]), "r"((a)[3]),                 \
          "r"(b0v), "r"(b1v))

// ---------------- weight prep: tf32 rounding of the two MMA weights ----------------
__global__ void prep_kernel(const float* __restrict__ re_w1,
                            const float* __restrict__ rp_w) {
    int m = blockIdx.x;
    int t = threadIdx.x;
    if (m == 0) {
        for (int i = t; i < 128 * 128; i += 256) g_w1k[i] = to_tf32(re_w1[i]);
    } else {
        for (int i = t; i < 128 * 128; i += 256) {
            int f = i >> 7, k = i & 127;
            g_wrk[i] = to_tf32(rp_w[f * 384 + k]);
        }
    }
}

// ---------------- per-node parts of rel layer0: 8 nodes/block ----------------
__global__ __launch_bounds__(128) void node_pre_v2(const float* __restrict__ attrs,
                                                   const float* __restrict__ states,
                                                   const float* __restrict__ re_w0,
                                                   const float* __restrict__ re_b0) {
    __shared__ float sa[8][4];
    __shared__ float ss[8][8];
    int base = blockIdx.x * 8;
    int f = threadIdx.x;
    if (f < 32) {
        int n = f >> 2, c = f & 3;
        sa[n][c] = attrs[(base + n) * 4 + c];
    } else if (f < 96) {
        int q = f - 32;
        int n = q >> 3, c = q & 7;
        ss[n][c] = states[(base + n) * 8 + c];
    }
    __syncthreads();
    const float* w = re_w0 + f * 20;  // [rel(4) | dstate(8) | recv_attr(4) | send_attr(4)]
    float ws[8], wr4[4], ws4[4];
#pragma unroll
    for (int c = 0; c < 8; c++) ws[c] = w[4 + c];
#pragma unroll
    for (int c = 0; c < 4; c++) { wr4[c] = w[12 + c]; ws4[c] = w[16 + c]; }
    float b0 = re_b0[f];
    int b = base >> 6;
#pragma unroll
    for (int n = 0; n < 8; n++) {
        float u = b0, v = 0.f;
#pragma unroll
        for (int c = 0; c < 8; c++) {
            u += ws[c] * ss[n][c];
            v -= ws[c] * ss[n][c];
        }
#pragma unroll
        for (int c = 0; c < 4; c++) {
            u += wr4[c] * sa[n][c];
            v += ws4[c] * sa[n][c];
        }
        int node = base + n;
        g_u[node * 128 + f] = u;
        g_vt[(b * 128 + f) * 64 + (node & 63)] = v;
    }
}

// ---------------- object encoder: 8 nodes/block ----------------
__global__ __launch_bounds__(128) void obj_encode_v2(const float* __restrict__ attrs,
                                                     const float* __restrict__ states,
                                                     const float* __restrict__ oe_w0,
                                                     const float* __restrict__ oe_b0,
                                                     const float* __restrict__ oe_w1,
                                                     const float* __restrict__ oe_b1) {
    __shared__ float xs[8][12];
    __shared__ float Hs1[8][128];
    int base = blockIdx.x * 8;
    int f = threadIdx.x;
    if (f < 96) {
        int n = f / 12, c = f % 12;
        xs[n][c] = (c < 4) ? attrs[(base + n) * 4 + c] : states[(base + n) * 8 + (c - 4)];
    }
    __syncthreads();
    float w0r[12];
#pragma unroll
    for (int c = 0; c < 12; c++) w0r[c] = oe_w0[f * 12 + c];
    float b0 = oe_b0[f];
#pragma unroll
    for (int n = 0; n < 8; n++) {
        float h = b0;
#pragma unroll
        for (int c = 0; c < 12; c++) h += w0r[c] * xs[n][c];
        Hs1[n][f] = fmaxf(h, 0.f);
    }
    __syncthreads();
    float acc[8] = {0, 0, 0, 0, 0, 0, 0, 0};
#pragma unroll 4
    for (int k = 0; k < 128; k += 4) {
        float4 w = *(const float4*)&oe_w1[f * 128 + k];
#pragma unroll
        for (int n = 0; n < 8; n++) {
            float4 x = *(const float4*)&Hs1[n][k];
            acc[n] += w.x * x.x + w.y * x.y + w.z * x.z + w.w * x.w;
        }
    }
    float b1 = oe_b1[f];
#pragma unroll
    for (int n = 0; n < 8; n++)
        g_obj[(base + n) * 128 + f] = fmaxf(acc[n] + b1, 0.f);
}

// ---------------- fused relation encoder + edge-GEMM, 256 threads ----------------
__global__ __launch_bounds__(256) void rel_fused_tc(const float* __restrict__ rel_attrs,
                                                    const float* __restrict__ re_w0,
                                                    const float* __restrict__ re_b1) {
    extern __shared__ float dsm[];
    float* Hs = dsm;                    // 64 x 132
    float* Wsm = dsm + 8448;            // 128 x 132
    float* Us = dsm + 8448 + 16896;     // 128
    float* Bs = Us + 128;               // 128
    int bi = blockIdx.x, tid = threadIdx.x, b = bi >> 6;
    int lane = tid & 31, warp = tid >> 5;
    int jg = warp & 3;    // j-quarter: rows 16*jg..+15
    int ng = warp >> 2;   // f-half: cols 64*ng..+63
    uint32_t hs_base = (uint32_t)__cvta_generic_to_shared(Hs);
    uint32_t w_base = (uint32_t)__cvta_generic_to_shared(Wsm);

    if (tid < 128) {
        Us[tid] = g_u[bi * 128 + tid];
        Bs[tid] = re_b1[tid];
    }
    // load W1 (coalesced) into smem [f][k] stride 132
#pragma unroll 4
    for (int i = 0; i < 16; i++) {
        int idx = (i * 256 + tid) * 4;
        float4 v = *(const float4*)&g_w1k[idx];
        *(float4*)&Wsm[(idx >> 7) * 132 + (idx & 127)] = v;
    }
    __syncthreads();

    // ---- build H[j][k] (tf32): 4 threads per j, 32 k each ----
    {
        int j = tid & 63, kh = tid >> 6;
        float4 rv = *(const float4*)(rel_attrs + (bi * 64 + j) * 4);
        const float* vt = g_vt + b * 8192 + j;
#pragma unroll 4
        for (int kk = 0; kk < 32; kk++) {
            int k = kh * 32 + kk;
            const float* w = re_w0 + k * 20;
            float val = Us[k] + vt[k * 64] + rv.x * w[0] + rv.y * w[1] + rv.z * w[2] + rv.w * w[3];
            Hs[j * 132 + k] = to_tf32(fmaxf(val, 0.f));
        }
    }
    __syncthreads();

    // ldmatrix address components
    uint32_t aAddr = hs_base + 4 * ((16 * jg + (lane & 15)) * 132 + 4 * (lane >> 4));
    uint32_t bAddr = w_base + 4 * ((64 * ng + (lane & 7)) * 132 + 4 * (lane >> 3));
    float d[8][4];

    // ================= GEMM1: rel = relu(b1 + H @ W1^T) =================
#pragma unroll
    for (int n = 0; n < 8; n++)
#pragma unroll
        for (int q = 0; q < 4; q++) d[n][q] = 0.f;
#pragma unroll
    for (int c = 0; c < 8; c++) {
        int k0 = c * 16;
        uint32_t a[2][4];
        LDSM_X4(a[0], aAddr + 4 * k0);
        LDSM_X4(a[1], aAddr + 4 * (k0 + 8));
        uint32_t bb[8][4];
#pragma unroll
        for (int n = 0; n < 8; n++)
            LDSM_X4(bb[n], bAddr + 4 * (n * 8 * 132 + k0));
#pragma unroll
        for (int s = 0; s < 2; s++)
#pragma unroll
            for (int n = 0; n < 8; n++)
                MMA_TF32(d[n], a[s], bb[n][2 * s], bb[n][2 * s + 1]);
    }
    __syncthreads();  // all Hs / Wsm reads of GEMM1 complete

    // epilogue 1: bias + relu + tf32, rel[j][f] into Hs; also load Wr into Wsm
    {
        int r0 = 16 * jg + (lane >> 2);
#pragma unroll
        for (int n = 0; n < 8; n++) {
            int f0 = 64 * ng + 8 * n + 2 * (lane & 3);
            float bb0 = Bs[f0], bb1 = Bs[f0 + 1];
            Hs[r0 * 132 + f0]           = to_tf32(fmaxf(d[n][0] + bb0, 0.f));
            Hs[r0 * 132 + f0 + 1]       = to_tf32(fmaxf(d[n][1] + bb1, 0.f));
            Hs[(r0 + 8) * 132 + f0]     = to_tf32(fmaxf(d[n][2] + bb0, 0.f));
            Hs[(r0 + 8) * 132 + f0 + 1] = to_tf32(fmaxf(d[n][3] + bb1, 0.f));
        }
    }
#pragma unroll 4
    for (int i = 0; i < 16; i++) {
        int idx = (i * 256 + tid) * 4;
        float4 v = *(const float4*)&g_wrk[idx];
        *(float4*)&Wsm[(idx >> 7) * 132 + (idx & 127)] = v;
    }
    __syncthreads();

    // ================= GEMM2: E = rel @ Wr^T =================
#pragma unroll
    for (int n = 0; n < 8; n++)
#pragma unroll
        for (int q = 0; q < 4; q++) d[n][q] = 0.f;
#pragma unroll
    for (int c = 0; c < 8; c++) {
        int k0 = c * 16;
        uint32_t a[2][4];
        LDSM_X4(a[0], aAddr + 4 * k0);
        LDSM_X4(a[1], aAddr + 4 * (k0 + 8));
        uint32_t bb[8][4];
#pragma unroll
        for (int n = 0; n < 8; n++)
            LDSM_X4(bb[n], bAddr + 4 * (n * 8 * 132 + k0));
#pragma unroll
        for (int s = 0; s < 2; s++)
#pragma unroll
            for (int n = 0; n < 8; n++)
                MMA_TF32(d[n], a[s], bb[n][2 * s], bb[n][2 * s + 1]);
    }
    // epilogue 2: store E
    float* Ep = g_E + (long)bi * 8192;
    {
        int r0 = 16 * jg + (lane >> 2);
#pragma unroll
        for (int n = 0; n < 8; n++) {
            int f0 = 64 * ng + 8 * n + 2 * (lane & 3);
            *(float2*)&Ep[r0 * 128 + f0] = make_float2(d[n][0], d[n][1]);
            *(float2*)&Ep[(r0 + 8) * 128 + f0] = make_float2(d[n][2], d[n][3]);
        }
    }
}

// ---------------- R/S precompute: 8 nodes/block ----------------
__global__ __launch_bounds__(128) void rs_v2(const float* __restrict__ rp_w,
                                             const float* __restrict__ rp_b) {
    __shared__ float Os[8][128];
    int base = blockIdx.x * 8;
    int f = threadIdx.x;
#pragma unroll
    for (int n = 0; n < 8; n++) Os[n][f] = g_obj[(base + n) * 128 + f];
    __syncthreads();
    float r[8] = {0, 0, 0, 0, 0, 0, 0, 0};
    float s[8] = {0, 0, 0, 0, 0, 0, 0, 0};
    const float* wrow = rp_w + f * 384;
#pragma unroll 4
    for (int k = 0; k < 128; k += 4) {
        float4 wr = *(const float4*)&wrow[128 + k];
        float4 ws = *(const float4*)&wrow[256 + k];
#pragma unroll
        for (int n = 0; n < 8; n++) {
            float4 o = *(const float4*)&Os[n][k];
            r[n] += wr.x * o.x + wr.y * o.y + wr.z * o.z + wr.w * o.w;
            s[n] += ws.x * o.x + ws.y * o.y + ws.z * o.z + ws.w * o.w;
        }
    }
    float bb = rp_b[f];
#pragma unroll
    for (int n = 0; n < 8; n++) {
        g_R[(base + n) * 128 + f] = r[n] + bb;
        g_S[(base + n) * 128 + f] = s[n];
    }
}

// ---------------- edge apply: Y = E + R_i + S_j, LN, relu, sum over j ----------------
__global__ __launch_bounds__(128) void edge_apply_kernel(const float* __restrict__ rp_lnw,
                                                         const float* __restrict__ rp_lnb) {
    __shared__ float Rs[128];
    __shared__ float Ps[512];
    int bi = blockIdx.x;
    int tid = threadIdx.x;
    int b = bi >> 6;
    int warp = tid >> 5, lane = tid & 31;
    Rs[tid] = g_R[bi * 128 + tid];
    __syncthreads();
    float4 rv = *(const float4*)&Rs[lane * 4];
    float4 lw = *(const float4*)&rp_lnw[lane * 4];
    float4 lb = *(const float4*)&rp_lnb[lane * 4];
    const float* Ep = g_E + (long)bi * 8192;
    float ag0 = 0.f, ag1 = 0.f, ag2 = 0.f, ag3 = 0.f;
#pragma unroll 4
    for (int r = 0; r < 16; r++) {
        int j = warp * 16 + r;
        float4 e = *(const float4*)&Ep[j * 128 + lane * 4];
        float4 sv = *(const float4*)&g_S[(b * 64 + j) * 128 + lane * 4];
        float4 y = make_float4(e.x + rv.x + sv.x, e.y + rv.y + sv.y,
                               e.z + rv.z + sv.z, e.w + rv.w + sv.w);
        float s = y.x + y.y + y.z + y.w;
        float ss = y.x * y.x + y.y * y.y + y.z * y.z + y.w * y.w;
#pragma unroll
        for (int off = 16; off; off >>= 1) {
            s += __shfl_xor_sync(0xffffffffu, s, off);
            ss += __shfl_xor_sync(0xffffffffu, ss, off);
        }
        float mu = s * 0.0078125f;
        float var = ss * 0.0078125f - mu * mu;
        float rstd = rsqrtf(var + 1e-5f);
        ag0 += fmaxf((y.x - mu) * rstd * lw.x + lb.x, 0.f);
        ag1 += fmaxf((y.y - mu) * rstd * lw.y + lb.y, 0.f);
        ag2 += fmaxf((y.z - mu) * rstd * lw.z + lb.z, 0.f);
        ag3 += fmaxf((y.w - mu) * rstd * lw.w + lb.w, 0.f);
    }
    *(float4*)&Ps[warp * 128 + lane * 4] = make_float4(ag0, ag1, ag2, ag3);
    __syncthreads();
    g_agg[bi * 128 + tid] = Ps[tid] + Ps[128 + tid] + Ps[256 + tid] + Ps[384 + tid];
}

// ---------------- object update: 8 nodes/block ----------------
__global__ __launch_bounds__(128) void obj_update_v2(const float* __restrict__ pp_w,
                                                     const float* __restrict__ pp_b,
                                                     const float* __restrict__ pp_lnw,
                                                     const float* __restrict__ pp_lnb) {
    __shared__ float Xs[8][256];
    __shared__ float Cs[8][132];
    int base = blockIdx.x * 8;
    int f = threadIdx.x;
#pragma unroll
    for (int n = 0; n < 8; n++) {
        Xs[n][f] = g_obj[(base + n) * 128 + f];
        Xs[n][128 + f] = g_agg[(base + n) * 128 + f];
    }
    __syncthreads();
    float acc[8] = {0, 0, 0, 0, 0, 0, 0, 0};
    const float* wrow = pp_w + f * 256;
#pragma unroll 4
    for (int k = 0; k < 256; k += 4) {
        float4 w = *(const float4*)&wrow[k];
#pragma unroll
        for (int n = 0; n < 8; n++) {
            float4 x = *(const float4*)&Xs[n][k];
            acc[n] += w.x * x.x + w.y * x.y + w.z * x.z + w.w * x.w;
        }
    }
    float bb = pp_b[f];
#pragma unroll
    for (int n = 0; n < 8; n++) Cs[n][f] = acc[n] + bb;
    __syncthreads();
    int warp = f >> 5, lane = f & 31;
    float4 lw = *(const float4*)&pp_lnw[lane * 4];
    float4 lb = *(const float4*)&pp_lnb[lane * 4];
#pragma unroll
    for (int r = 0; r < 2; r++) {
        int n = warp * 2 + r;
        float4 y = *(const float4*)&Cs[n][lane * 4];
        float s = y.x + y.y + y.z + y.w;
        float ss = y.x * y.x + y.y * y.y + y.z * y.z + y.w * y.w;
#pragma unroll
        for (int off = 16; off; off >>= 1) {
            s += __shfl_xor_sync(0xffffffffu, s, off);
            ss += __shfl_xor_sync(0xffffffffu, ss, off);
        }
        float mu = s * 0.0078125f;
        float var = ss * 0.0078125f - mu * mu;
        float rstd = rsqrtf(var + 1e-5f);
        float4 o = make_float4(fmaxf((y.x - mu) * rstd * lw.x + lb.x, 0.f),
                               fmaxf((y.y - mu) * rstd * lw.y + lb.y, 0.f),
                               fmaxf((y.z - mu) * rstd * lw.z + lb.z, 0.f),
                               fmaxf((y.w - mu) * rstd * lw.w + lb.w, 0.f));
        *(float4*)&g_obj[(base + n) * 128 + lane * 4] = o;
    }
}

// ---------------- prediction head: 8 nodes/block ----------------
__global__ __launch_bounds__(128) void predict_v2(const float* __restrict__ pr_w0,
                                                  const float* __restrict__ pr_b0,
                                                  const float* __restrict__ pr_w1,
                                                  const float* __restrict__ pr_b1,
                                                  float* __restrict__ out) {
    __shared__ float Xs[8][128];
    __shared__ float Hs2[8][128];
    int base = blockIdx.x * 8;
    int f = threadIdx.x;
#pragma unroll
    for (int n = 0; n < 8; n++) Xs[n][f] = g_obj[(base + n) * 128 + f];
    __syncthreads();
    float acc[8] = {0, 0, 0, 0, 0, 0, 0, 0};
    const float* wrow = pr_w0 + f * 128;
#pragma unroll 4
    for (int k = 0; k < 128; k += 4) {
        float4 w = *(const float4*)&wrow[k];
#pragma unroll
        for (int n = 0; n < 8; n++) {
            float4 x = *(const float4*)&Xs[n][k];
            acc[n] += w.x * x.x + w.y * x.y + w.z * x.z + w.w * x.w;
        }
    }
    float b0 = pr_b0[f];
#pragma unroll
    for (int n = 0; n < 8; n++) Hs2[n][f] = fmaxf(acc[n] + b0, 0.f);
    __syncthreads();
    // layer2: 8 nodes x 32 outs = 256 outputs, 2 per thread
    int n = f >> 4, op = f & 15;
    float a0 = 0.f, a1 = 0.f;
    const float* w0p = pr_w1 + (2 * op) * 128;
    const float* w1p = pr_w1 + (2 * op + 1) * 128;
#pragma unroll 4
    for (int k = 0; k < 128; k += 4) {
        float4 x = *(const float4*)&Hs2[n][k];
        float4 wa = *(const float4*)&w0p[k];
        float4 wb = *(const float4*)&w1p[k];
        a0 += wa.x * x.x + wa.y * x.y + wa.z * x.z + wa.w * x.w;
        a1 += wb.x * x.x + wb.y * x.y + wb.z * x.z + wb.w * x.w;
    }
    out[(base + n) * 32 + 2 * op]     = tanhf(a0 + pr_b1[2 * op]);
    out[(base + n) * 32 + 2 * op + 1] = tanhf(a1 + pr_b1[2 * op + 1]);
}

// ---------------- launch ----------------
extern "C" void kernel_launch(void* const* d_in, const int* in_sizes, int n_in,
                              void* d_out, int out_size) {
    const float* attrs     = (const float*)d_in[0];
    const float* states    = (const float*)d_in[1];
    const float* rel_attrs = (const float*)d_in[3];
    const float* oe_w0 = (const float*)d_in[4];
    const float* oe_b0 = (const float*)d_in[5];
    const float* oe_w1 = (const float*)d_in[6];
    const float* oe_b1 = (const float*)d_in[7];
    const float* re_w0 = (const float*)d_in[8];
    const float* re_b0 = (const float*)d_in[9];
    const float* re_w1 = (const float*)d_in[10];
    const float* re_b1 = (const float*)d_in[11];
    const float* rp_w  = (const float*)d_in[12];
    const float* rp_b  = (const float*)d_in[13];
    const float* rp_lnw = (const float*)d_in[14];
    const float* rp_lnb = (const float*)d_in[15];
    const float* pp_w  = (const float*)d_in[16];
    const float* pp_b  = (const float*)d_in[17];
    const float* pp_lnw = (const float*)d_in[18];
    const float* pp_lnb = (const float*)d_in[19];
    const float* pr_w0 = (const float*)d_in[20];
    const float* pr_b0 = (const float*)d_in[21];
    const float* pr_w1 = (const float*)d_in[22];
    const float* pr_b1 = (const float*)d_in[23];
    float* out = (float*)d_out;

    const int dsm_bytes = (8448 + 16896 + 256) * 4;  // ~102.4 KB
    cudaFuncSetAttribute(rel_fused_tc, cudaFuncAttributeMaxDynamicSharedMemorySize, dsm_bytes);

    prep_kernel<<<2, 256>>>(re_w1, rp_w);
    node_pre_v2<<<256, 128>>>(attrs, states, re_w0, re_b0);
    obj_encode_v2<<<256, 128>>>(attrs, states, oe_w0, oe_b0, oe_w1, oe_b1);
    rel_fused_tc<<<NNODES, 256, dsm_bytes>>>(rel_attrs, re_w0, re_b1);
    for (int step = 0; step < 2; step++) {
        rs_v2<<<256, 128>>>(rp_w, rp_b);
        edge_apply_kernel<<<NNODES, 128>>>(rp_lnw, rp_lnb);
        obj_update_v2<<<256, 128>>>(pp_w, pp_b, pp_lnw, pp_lnb);
    }
    predict_v2<<<256, 128>>>(pr_w0, pr_b0, pr_w1, pr_b1, out);
}